// round 14
// baseline (speedup 1.0000x reference)
#include <cuda_runtime.h>
#include <cuda_fp16.h>
#include <cstdint>
#include <cstddef>

// ---------------------------------------------------------------------------
// Problem constants
// ---------------------------------------------------------------------------
constexpr int NB = 4096;
constexpr int ND = 512;
constexpr int NH = 2048;
constexpr int NSTATE = NB * ND;
constexpr int NSTEPS = 20;
constexpr int NCORR  = 3;

// ---------------------------------------------------------------------------
// Scratch (device globals)
// ---------------------------------------------------------------------------
__device__ float g_y[NSTATE];
__device__ float g_acc[NSTATE];
__device__ float g_kk[NSTATE];
__device__ float g_pred[NSTATE];
__device__ float g_base[NSTATE];
__device__ float g_hist[4 * NSTATE];
__device__ float g_part[2 * NSTATE];            // split-K partials for gemm2

__device__ __half g_pin_hi[NSTATE];             // feval input planes (fp16)
__device__ __half g_pin_lo[NSTATE];
__device__ __half g_w1t[(size_t)NH * ND];       // weights: single fp16 plane
__device__ __half g_w2t[(size_t)ND * NH];
__device__ __half g_act_hi[(size_t)NB * NH];
__device__ __half g_act_lo[(size_t)NB * NH];

// ---------------------------------------------------------------------------
// Helpers
// ---------------------------------------------------------------------------
__device__ __forceinline__ uint32_t smem_u32(const void* p) {
    uint32_t a;
    asm("{ .reg .u64 t; cvta.to.shared.u64 t, %1; cvt.u32.u64 %0, t; }"
        : "=r"(a) : "l"(p));
    return a;
}

__device__ __forceinline__ uint32_t swz(uint32_t o) {
    return o ^ ((o >> 3) & 0x70);
}

__device__ __forceinline__ void cpa16(uint32_t s, const void* g) {
    asm volatile("cp.async.cg.shared.global [%0], [%1], 16;" :: "r"(s), "l"(g));
}

__device__ __forceinline__ void ldmx4(uint32_t r[4], uint32_t addr) {
    asm volatile("ldmatrix.sync.aligned.m8n8.x4.shared.b16 {%0,%1,%2,%3}, [%4];"
                 : "=r"(r[0]), "=r"(r[1]), "=r"(r[2]), "=r"(r[3]) : "r"(addr));
}

__device__ __forceinline__ void mma16816(float d[4], const uint32_t a[4],
                                         uint32_t b0, uint32_t b1) {
    asm volatile(
        "mma.sync.aligned.m16n8k16.row.col.f32.f16.f16.f32 "
        "{%0,%1,%2,%3}, {%4,%5,%6,%7}, {%8,%9}, {%0,%1,%2,%3};"
        : "+f"(d[0]), "+f"(d[1]), "+f"(d[2]), "+f"(d[3])
        : "r"(a[0]), "r"(a[1]), "r"(a[2]), "r"(a[3]), "r"(b0), "r"(b1));
}

__device__ __forceinline__ uint32_t pk2h(__half a, __half b) {
    __half2 t = __halves2half2(a, b);
    return *reinterpret_cast<uint32_t*>(&t);
}
__device__ __forceinline__ void split1h(float v, __half& h, __half& l) {
    h = __float2half_rn(v);
    l = __float2half_rn(v - __half2float(h));
}
__device__ __forceinline__ void split4h(float4 v, uint2& oh, uint2& ol) {
    __half h0, h1, h2, h3, l0, l1, l2, l3;
    split1h(v.x, h0, l0); split1h(v.y, h1, l1);
    split1h(v.z, h2, l2); split1h(v.w, h3, l3);
    oh.x = pk2h(h0, h1); oh.y = pk2h(h2, h3);
    ol.x = pk2h(l0, l1); ol.y = pk2h(l2, l3);
}

// ---------------------------------------------------------------------------
// fp16 2-product split HMMA GEMM (A = hi+lo fp16 planes, B = single fp16).
// CTA tile 128x128, 8 warps of 32x64, 2 CTAs/SM. 2-stage cp.async.
// Compute restructured into half-slices (B np-pairs of 8 regs) so the full
// fragment DAG fits in <128 live regs and ptxas can overlap LDSM with MMAs.
//   EPI 0: C = tanh(acc + bias) -> fp16 hi/lo planes
//   EPI 1: partial fp32 store (split-K slice via blockIdx.z)
// SMEM/stage: A 2x16KB + B 16KB = 48KB; 2 stages = 96KB; x2 CTAs = 192KB/SM.
// ---------------------------------------------------------------------------
constexpr int STAGE_B = 49152;
constexpr int GEMM_SMEM = 2 * STAGE_B;   // 98304

template <int EPI>
__global__ __launch_bounds__(256, 2)
void gemm_cp(const __half* __restrict__ Ah,
             const __half* __restrict__ Al, int lda,
             const __half* __restrict__ Bp, int ldb,
             int nchunks, int kslice,
             const float* __restrict__ bias,
             __half* __restrict__ Chi,
             __half* __restrict__ Clo,
             float* __restrict__ Cp,
             int N)
{
    extern __shared__ char smem[];
    const uint32_t sbase = smem_u32(smem);
    const int tid = threadIdx.x;
    const int wid = tid >> 5, lane = tid & 31;
    const int wm = wid & 3;            // 4 row-blocks of 32
    const int wn = wid >> 2;           // 2 col-blocks of 64
    const int bm = blockIdx.y * 128, bn = blockIdx.x * 128;
    const int koff = blockIdx.z * kslice;
    if (EPI == 1) Cp += (size_t)blockIdx.z * NSTATE;

    // cp.async per-thread mapping: row cr (+i*32), 16B-col cq
    const int cr = tid >> 3;
    const int cq = tid & 7;
    const uint32_t so0 = swz((uint32_t)cr * 128 + cq * 16);

    // incremental global pointers
    const __half* pAh = Ah + (size_t)(bm + cr) * lda + koff + cq * 8;
    const __half* pAl = Al + (size_t)(bm + cr) * lda + koff + cq * 8;
    const __half* pB  = Bp + (size_t)(bn + cr) * ldb + koff + cq * 8;

    const int bg = lane >> 3;
    const uint32_t boffl = (uint32_t)((lane & 7) + ((bg & 2) ? 8 : 0)) * 128
                         + (bg & 1) * 16;
    const uint32_t aoffl = (uint32_t)(lane & 15) * 128 + (lane >> 4) * 16;

    float acc[2][8][4];
    #pragma unroll
    for (int mt = 0; mt < 2; mt++)
        #pragma unroll
        for (int nt = 0; nt < 8; nt++)
            #pragma unroll
            for (int q = 0; q < 4; q++) acc[mt][nt][q] = 0.f;

    auto issue = [&](int c) {
        const uint32_t s = sbase + (uint32_t)(c & 1) * STAGE_B;
        const int k0 = c << 6;
        #pragma unroll
        for (int i = 0; i < 4; i++) {            // A: 128 rows, 2 planes
            const uint32_t so = so0 + (uint32_t)i * 32 * 128;
            cpa16(s + so,         pAh + (size_t)i * 32 * lda + k0);
            cpa16(s + 16384 + so, pAl + (size_t)i * 32 * lda + k0);
        }
        #pragma unroll
        for (int i = 0; i < 4; i++) {            // B: 128 rows, 1 plane
            const uint32_t so = so0 + (uint32_t)i * 32 * 128;
            cpa16(s + 32768 + so, pB + (size_t)i * 32 * ldb + k0);
        }
        asm volatile("cp.async.commit_group;");
    };

    auto compute = [&](int st) {
        const uint32_t sa_h = sbase + (uint32_t)st * STAGE_B;
        const uint32_t sa_l = sa_h + 16384;
        const uint32_t sb   = sa_h + 32768;
        #pragma unroll
        for (int ks = 0; ks < 4; ks++) {
            const uint32_t kb = ks * 32;
            uint32_t ah[2][4], al2[2][4];
            #pragma unroll
            for (int mt = 0; mt < 2; mt++) {
                const uint32_t o = aoffl + (uint32_t)(wm * 32 + mt * 16) * 128 + kb;
                ldmx4(ah[mt],  sa_h + swz(o));
                ldmx4(al2[mt], sa_l + swz(o));
            }
            // B processed in two np-pairs (8 frag regs live at a time) so the
            // next pair's LDSM can overlap this pair's MMA burst.
            #pragma unroll
            for (int half = 0; half < 2; half++) {
                uint32_t bb[2][4];
                #pragma unroll
                for (int p = 0; p < 2; p++) {
                    const int np = half * 2 + p;
                    const uint32_t o = boffl + (uint32_t)(wn * 64 + np * 16) * 128 + kb;
                    ldmx4(bb[p], sb + swz(o));
                }
                // hi-product stream (8 MMAs), then lo-product stream:
                // same-accumulator distance = 8 MMAs.
                #pragma unroll
                for (int mt = 0; mt < 2; mt++)
                    #pragma unroll
                    for (int p = 0; p < 2; p++)
                        #pragma unroll
                        for (int h2 = 0; h2 < 2; h2++)
                            mma16816(acc[mt][(half * 2 + p) * 2 + h2], ah[mt],
                                     bb[p][h2 * 2], bb[p][h2 * 2 + 1]);
                #pragma unroll
                for (int mt = 0; mt < 2; mt++)
                    #pragma unroll
                    for (int p = 0; p < 2; p++)
                        #pragma unroll
                        for (int h2 = 0; h2 < 2; h2++)
                            mma16816(acc[mt][(half * 2 + p) * 2 + h2], al2[mt],
                                     bb[p][h2 * 2], bb[p][h2 * 2 + 1]);
            }
        }
    };

    issue(0);
    for (int c = 0; c < nchunks; c++) {
        asm volatile("cp.async.wait_group 0;" ::: "memory");
        __syncthreads();
        if (c + 1 < nchunks) issue(c + 1);
        compute(c & 1);
    }

    // ---- epilogue ----
    const int r0l = lane >> 2, c0l = (lane & 3) * 2;
    #pragma unroll
    for (int mt = 0; mt < 2; mt++) {
        const int rowA = bm + wm * 32 + mt * 16 + r0l;
        #pragma unroll
        for (int nt = 0; nt < 8; nt++) {
            const int col = bn + wn * 64 + nt * 8 + c0l;
            #pragma unroll
            for (int half2i = 0; half2i < 2; half2i++) {
                const int row = rowA + half2i * 8;
                float v0 = acc[mt][nt][half2i * 2 + 0];
                float v1 = acc[mt][nt][half2i * 2 + 1];
                if (EPI == 0) {
                    const float2 bbv = *(const float2*)(bias + col);
                    v0 = tanhf(v0 + bbv.x); v1 = tanhf(v1 + bbv.y);
                    __half h0, l0, h1, l1;
                    split1h(v0, h0, l0); split1h(v1, h1, l1);
                    *(uint32_t*)(Chi + (size_t)row * N + col) = pk2h(h0, h1);
                    *(uint32_t*)(Clo + (size_t)row * N + col) = pk2h(l0, l1);
                } else {
                    *(float2*)(Cp + (size_t)row * N + col) = make_float2(v0, v1);
                }
            }
        }
    }
}

// ---------------------------------------------------------------------------
// Weight transpose to single fp16 plane: W[K][N] -> T[N][K]
// ---------------------------------------------------------------------------
__global__ void k_tsplit(const float* __restrict__ W,
                         __half* __restrict__ T, int K, int N)
{
    __shared__ float t[32][33];
    const int n0 = blockIdx.x * 32, k0 = blockIdx.y * 32;
    for (int i = threadIdx.y; i < 32; i += 8)
        t[i][threadIdx.x] = W[(size_t)(k0 + i) * N + n0 + threadIdx.x];
    __syncthreads();
    for (int i = threadIdx.y; i < 32; i += 8) {
        float v = t[threadIdx.x][i];
        T[(size_t)(n0 + i) * K + k0 + threadIdx.x] = __float2half_rn(v);
    }
}

// ---------------------------------------------------------------------------
// Combine: dst = alpha*(p0+p1+bias) [+ addv], optional fp16 planes of dst
// ---------------------------------------------------------------------------
__global__ void k_comb(float4* __restrict__ dst,
                       const float4* __restrict__ p0, const float4* __restrict__ p1,
                       const float4* __restrict__ bias4,
                       const float4* __restrict__ addv, float alpha,
                       uint2* __restrict__ oh, uint2* __restrict__ ol)
{
    int i = blockIdx.x * 256 + threadIdx.x;
    float4 a = p0[i], b = p1[i], bb = bias4[i & 127];
    float4 v;
    v.x = alpha * (a.x + b.x + bb.x);
    v.y = alpha * (a.y + b.y + bb.y);
    v.z = alpha * (a.z + b.z + bb.z);
    v.w = alpha * (a.w + b.w + bb.w);
    if (addv) {
        float4 av = addv[i];
        v.x += av.x; v.y += av.y; v.z += av.z; v.w += av.w;
    }
    dst[i] = v;
    if (oh) {
        uint2 h2, l2; split4h(v, h2, l2);
        oh[i] = h2; ol[i] = l2;
    }
}

// ---------------------------------------------------------------------------
// Elementwise kernels
// ---------------------------------------------------------------------------
__global__ void k_split(float4* __restrict__ o, uint2* __restrict__ oh,
                        uint2* __restrict__ ol, const float4* __restrict__ src)
{
    int i = blockIdx.x * 256 + threadIdx.x;
    float4 v = src[i];
    o[i] = v;
    uint2 h2, l2; split4h(v, h2, l2);
    oh[i] = h2; ol[i] = l2;
}

__global__ void k_axpy(float4* __restrict__ o, const float4* __restrict__ y,
                       const float4* __restrict__ k, float a)
{
    int i = blockIdx.x * 256 + threadIdx.x;
    float4 yv = y[i], kv = k[i];
    o[i] = make_float4(fmaf(a, kv.x, yv.x), fmaf(a, kv.y, yv.y),
                       fmaf(a, kv.z, yv.z), fmaf(a, kv.w, yv.w));
}

__global__ void k_axpy_sp(uint2* __restrict__ oh, uint2* __restrict__ ol,
                          const float4* __restrict__ y,
                          const float4* __restrict__ k, float a)
{
    int i = blockIdx.x * 256 + threadIdx.x;
    float4 yv = y[i], kv = k[i];
    float4 v = make_float4(fmaf(a, kv.x, yv.x), fmaf(a, kv.y, yv.y),
                           fmaf(a, kv.z, yv.z), fmaf(a, kv.w, yv.w));
    uint2 h2, l2; split4h(v, h2, l2);
    oh[i] = h2; ol[i] = l2;
}

__global__ void k_acc(float4* __restrict__ o, const float4* __restrict__ p, float a)
{
    int i = blockIdx.x * 256 + threadIdx.x;
    float4 ov = o[i], pv = p[i];
    o[i] = make_float4(fmaf(a, pv.x, ov.x), fmaf(a, pv.y, ov.y),
                       fmaf(a, pv.z, ov.z), fmaf(a, pv.w, ov.w));
}

__global__ void k_acc_sp(float4* __restrict__ o, const float4* __restrict__ p,
                         float a, uint2* __restrict__ oh, uint2* __restrict__ ol)
{
    int i = blockIdx.x * 256 + threadIdx.x;
    float4 ov = o[i], pv = p[i];
    float4 v = make_float4(fmaf(a, pv.x, ov.x), fmaf(a, pv.y, ov.y),
                           fmaf(a, pv.z, ov.z), fmaf(a, pv.w, ov.w));
    o[i] = v;
    uint2 h2, l2; split4h(v, h2, l2);
    oh[i] = h2; ol[i] = l2;
}

__global__ void k_pred_sp(float4* __restrict__ o, const float4* __restrict__ y,
                          const float4* __restrict__ h0, const float4* __restrict__ h1,
                          const float4* __restrict__ h2, const float4* __restrict__ h3,
                          float c, uint2* __restrict__ oh, uint2* __restrict__ ol)
{
    int i = blockIdx.x * 256 + threadIdx.x;
    float4 yv = y[i], a = h0[i], b = h1[i], d = h2[i], e = h3[i];
    float4 r;
    r.x = yv.x + c * (55.f * a.x - 59.f * b.x + 37.f * d.x - 9.f * e.x);
    r.y = yv.y + c * (55.f * a.y - 59.f * b.y + 37.f * d.y - 9.f * e.y);
    r.z = yv.z + c * (55.f * a.z - 59.f * b.z + 37.f * d.z - 9.f * e.z);
    r.w = yv.w + c * (55.f * a.w - 59.f * b.w + 37.f * d.w - 9.f * e.w);
    o[i] = r;
    uint2 h2p, l2p; split4h(r, h2p, l2p);
    oh[i] = h2p; ol[i] = l2p;
}

__global__ void k_base(float4* __restrict__ o, const float4* __restrict__ y,
                       const float4* __restrict__ h0, const float4* __restrict__ h1,
                       const float4* __restrict__ h2, float c)
{
    int i = blockIdx.x * 256 + threadIdx.x;
    float4 yv = y[i], a = h0[i], b = h1[i], d = h2[i];
    float4 r;
    r.x = yv.x + c * (19.f * a.x - 5.f * b.x + d.x);
    r.y = yv.y + c * (19.f * a.y - 5.f * b.y + d.y);
    r.z = yv.z + c * (19.f * a.z - 5.f * b.z + d.z);
    r.w = yv.w + c * (19.f * a.w - 5.f * b.w + d.w);
    o[i] = r;
}

// ---------------------------------------------------------------------------
// Host orchestration
// ---------------------------------------------------------------------------
extern "C" void kernel_launch(void* const* d_in, const int* in_sizes, int n_in,
                              void* d_out, int out_size)
{
    const float* x  = (const float*)d_in[0];
    const float* W1 = (const float*)d_in[1];
    const float* b1 = (const float*)d_in[2];
    const float* W2 = (const float*)d_in[3];
    const float* b2 = (const float*)d_in[4];
    float* out = (float*)d_out;

    float *y, *acc, *kk, *pred, *base, *histbase, *part;
    __half *pinh, *pinl, *w1t, *w2t, *ah, *al;
    cudaGetSymbolAddress((void**)&y,        g_y);
    cudaGetSymbolAddress((void**)&acc,      g_acc);
    cudaGetSymbolAddress((void**)&kk,       g_kk);
    cudaGetSymbolAddress((void**)&pred,     g_pred);
    cudaGetSymbolAddress((void**)&base,     g_base);
    cudaGetSymbolAddress((void**)&histbase, g_hist);
    cudaGetSymbolAddress((void**)&part,     g_part);
    cudaGetSymbolAddress((void**)&pinh,     g_pin_hi);
    cudaGetSymbolAddress((void**)&pinl,     g_pin_lo);
    cudaGetSymbolAddress((void**)&w1t,      g_w1t);
    cudaGetSymbolAddress((void**)&w2t,      g_w2t);
    cudaGetSymbolAddress((void**)&ah,       g_act_hi);
    cudaGetSymbolAddress((void**)&al,       g_act_lo);

    cudaFuncSetAttribute(gemm_cp<0>, cudaFuncAttributeMaxDynamicSharedMemorySize, GEMM_SMEM);
    cudaFuncSetAttribute(gemm_cp<1>, cudaFuncAttributeMaxDynamicSharedMemorySize, GEMM_SMEM);

    float* h[4];
    for (int i = 0; i < 4; i++) h[i] = histbase + (size_t)i * NSTATE;

    const float dt = 1.0f / (float)NSTEPS;
    const float c  = dt / 24.0f;

    const dim3 blk(256);
    const dim3 grid1(NH / 128, NB / 128);        // 16 x 32 = 512 CTAs
    const dim3 grid2(ND / 128, NB / 128, 2);     // 4 x 32 x 2 = 256 CTAs
    const int EG = NSTATE / 4 / 256;

    k_tsplit<<<dim3(NH / 32, ND / 32), dim3(32, 8)>>>(W1, w1t, ND, NH);
    k_tsplit<<<dim3(ND / 32, NH / 32), dim3(32, 8)>>>(W2, w2t, NH, ND);

    auto feval = [&](float* dstF, __half* dsth, __half* dstl,
                     float alpha, const float* addv) {
        gemm_cp<0><<<grid1, blk, GEMM_SMEM>>>(pinh, pinl, ND, w1t, ND,
                                              ND / 64, 0, b1, ah, al, nullptr, NH);
        gemm_cp<1><<<grid2, blk, GEMM_SMEM>>>(ah, al, NH, w2t, NH,
                                              (NH / 2) / 64, NH / 2, nullptr,
                                              nullptr, nullptr, part, ND);
        k_comb<<<EG, blk>>>((float4*)dstF, (const float4*)part,
                            (const float4*)(part + NSTATE), (const float4*)b2,
                            (const float4*)addv, alpha, (uint2*)dsth, (uint2*)dstl);
    };

    // y = x (fp32 + planes)
    k_split<<<EG, blk>>>((float4*)y, (uint2*)pinh, (uint2*)pinl, (const float4*)x);

    // ---- bootstrap: f(y0) -> h[3] ----
    feval(h[3], nullptr, nullptr, 1.f, nullptr);

    // ---- 3 RK4 steps; k1 reused from most recent hist entry ----
    for (int s = 0; s < 3; s++) {
        float* k1 = h[3 - s];
        k_axpy   <<<EG, blk>>>((float4*)acc, (const float4*)y, (const float4*)k1, dt / 6.f);
        k_axpy_sp<<<EG, blk>>>((uint2*)pinh, (uint2*)pinl,
                               (const float4*)y, (const float4*)k1, 0.5f * dt);
        feval(kk, nullptr, nullptr, 1.f, nullptr);                           // k2
        k_acc    <<<EG, blk>>>((float4*)acc, (const float4*)kk, dt / 3.f);
        k_axpy_sp<<<EG, blk>>>((uint2*)pinh, (uint2*)pinl,
                               (const float4*)y, (const float4*)kk, 0.5f * dt);
        feval(kk, nullptr, nullptr, 1.f, nullptr);                           // k3
        k_acc    <<<EG, blk>>>((float4*)acc, (const float4*)kk, dt / 3.f);
        k_axpy_sp<<<EG, blk>>>((uint2*)pinh, (uint2*)pinl,
                               (const float4*)y, (const float4*)kk, dt);
        feval(kk, nullptr, nullptr, 1.f, nullptr);                           // k4
        k_acc_sp <<<EG, blk>>>((float4*)acc, (const float4*)kk, dt / 6.f,
                               (uint2*)pinh, (uint2*)pinl);
        { float* t = y; y = acc; acc = t; }
        feval(h[2 - s], nullptr, nullptr, 1.f, nullptr);     // f(y_new) = next k1
    }

    // ---- 17 ABM4 predictor-corrector steps ----
    const int NABM = NSTEPS - 3;
    for (int i = 0; i < NABM; i++) {
        k_pred_sp<<<EG, blk>>>((float4*)pred, (const float4*)y,
                               (const float4*)h[0], (const float4*)h[1],
                               (const float4*)h[2], (const float4*)h[3], c,
                               (uint2*)pinh, (uint2*)pinl);
        k_base<<<EG, blk>>>((float4*)base, (const float4*)y,
                            (const float4*)h[0], (const float4*)h[1],
                            (const float4*)h[2], c);
        for (int j = 0; j < NCORR; j++) {
            const bool last = (i == NABM - 1) && (j == NCORR - 1);
            if (last) feval(out,  nullptr, nullptr, 9.f * c, base);
            else      feval(pred, pinh,    pinl,    9.f * c, base);
        }
        if (i < NABM - 1) {
            feval(h[3], nullptr, nullptr, 1.f, nullptr);     // f(pred)
            float* t = h[3]; h[3] = h[2]; h[2] = h[1]; h[1] = h[0]; h[0] = t;
            float* t2 = y; y = pred; pred = t2;
        }
    }
}

// round 15
// speedup vs baseline: 1.6714x; 1.6714x over previous
#include <cuda_runtime.h>
#include <cuda_fp16.h>
#include <cstdint>
#include <cstddef>

// ---------------------------------------------------------------------------
// Problem constants
// ---------------------------------------------------------------------------
constexpr int NB = 4096;
constexpr int ND = 512;
constexpr int NH = 2048;
constexpr int NSTATE = NB * ND;
constexpr int NSTEPS = 20;
constexpr int NCORR  = 3;

// ---------------------------------------------------------------------------
// Scratch (device globals)
// ---------------------------------------------------------------------------
__device__ float g_y[NSTATE];
__device__ float g_acc[NSTATE];
__device__ float g_kk[NSTATE];
__device__ float g_pred[NSTATE];
__device__ float g_base[NSTATE];
__device__ float g_hist[4 * NSTATE];
__device__ float g_part[2 * NSTATE];            // split-K partials for gemm2

__device__ __half g_pin[NSTATE];                // feval input (fp16)
__device__ __half g_w1t[(size_t)NH * ND];       // W1^T fp16
__device__ __half g_w2t[(size_t)ND * NH];       // W2^T fp16
__device__ __half g_act[(size_t)NB * NH];       // tanh activations fp16

// ---------------------------------------------------------------------------
// Helpers
// ---------------------------------------------------------------------------
__device__ __forceinline__ uint32_t smem_u32(const void* p) {
    uint32_t a;
    asm("{ .reg .u64 t; cvta.to.shared.u64 t, %1; cvt.u32.u64 %0, t; }"
        : "=r"(a) : "l"(p));
    return a;
}

__device__ __forceinline__ uint32_t swz(uint32_t o) {
    return o ^ ((o >> 3) & 0x70);
}

__device__ __forceinline__ void cpa16(uint32_t s, const void* g) {
    asm volatile("cp.async.cg.shared.global [%0], [%1], 16;" :: "r"(s), "l"(g));
}

__device__ __forceinline__ void ldmx4(uint32_t r[4], uint32_t addr) {
    asm volatile("ldmatrix.sync.aligned.m8n8.x4.shared.b16 {%0,%1,%2,%3}, [%4];"
                 : "=r"(r[0]), "=r"(r[1]), "=r"(r[2]), "=r"(r[3]) : "r"(addr));
}

__device__ __forceinline__ void mma16816(float d[4], const uint32_t a[4],
                                         uint32_t b0, uint32_t b1) {
    asm volatile(
        "mma.sync.aligned.m16n8k16.row.col.f32.f16.f16.f32 "
        "{%0,%1,%2,%3}, {%4,%5,%6,%7}, {%8,%9}, {%0,%1,%2,%3};"
        : "+f"(d[0]), "+f"(d[1]), "+f"(d[2]), "+f"(d[3])
        : "r"(a[0]), "r"(a[1]), "r"(a[2]), "r"(a[3]), "r"(b0), "r"(b1));
}

__device__ __forceinline__ uint32_t pk2h(__half a, __half b) {
    __half2 t = __halves2half2(a, b);
    return *reinterpret_cast<uint32_t*>(&t);
}
__device__ __forceinline__ uint2 pk4h(float4 v) {
    uint2 r;
    r.x = pk2h(__float2half_rn(v.x), __float2half_rn(v.y));
    r.y = pk2h(__float2half_rn(v.z), __float2half_rn(v.w));
    return r;
}

// ---------------------------------------------------------------------------
// Single-product fp16 HMMA GEMM (A fp16, B fp16, fp32 accum).
// CTA tile 128x128, 8 warps of 32x64, 2 CTAs/SM. 3-stage cp.async ring.
//   EPI 0: C = tanh(acc + bias) -> fp16
//   EPI 1: partial fp32 store (split-K slice via blockIdx.z)
// SMEM/stage: A 16KB + B 16KB = 32KB; 3 stages = 96KB; x2 CTAs = 192KB/SM.
// ---------------------------------------------------------------------------
constexpr int STAGE_B = 32768;
constexpr int GEMM_SMEM = 3 * STAGE_B;   // 98304

template <int EPI>
__global__ __launch_bounds__(256, 2)
void gemm_cp(const __half* __restrict__ Ap, int lda,
             const __half* __restrict__ Bp, int ldb,
             int nchunks, int kslice,
             const float* __restrict__ bias,
             __half* __restrict__ Ch,
             float* __restrict__ Cp,
             int N)
{
    extern __shared__ char smem[];
    const uint32_t sbase = smem_u32(smem);
    const int tid = threadIdx.x;
    const int wid = tid >> 5, lane = tid & 31;
    const int wm = wid & 3;            // 4 row-blocks of 32
    const int wn = wid >> 2;           // 2 col-blocks of 64
    const int bm = blockIdx.y * 128, bn = blockIdx.x * 128;
    const int koff = blockIdx.z * kslice;
    if (EPI == 1) Cp += (size_t)blockIdx.z * NSTATE;

    // cp.async per-thread mapping: row cr (+i*32), 16B-col cq
    const int cr = tid >> 3;
    const int cq = tid & 7;
    const uint32_t so0 = swz((uint32_t)cr * 128 + cq * 16);

    const __half* pA = Ap + (size_t)(bm + cr) * lda + koff + cq * 8;
    const __half* pB = Bp + (size_t)(bn + cr) * ldb + koff + cq * 8;

    const int bg = lane >> 3;
    const uint32_t boffl = (uint32_t)((lane & 7) + ((bg & 2) ? 8 : 0)) * 128
                         + (bg & 1) * 16;
    const uint32_t aoffl = (uint32_t)(lane & 15) * 128 + (lane >> 4) * 16;

    float acc[2][8][4];
    #pragma unroll
    for (int mt = 0; mt < 2; mt++)
        #pragma unroll
        for (int nt = 0; nt < 8; nt++)
            #pragma unroll
            for (int q = 0; q < 4; q++) acc[mt][nt][q] = 0.f;

    auto issue = [&](int c) {
        const int st = c - (c / 3) * 3;
        const uint32_t s = sbase + (uint32_t)st * STAGE_B;
        const int k0 = c << 6;
        #pragma unroll
        for (int i = 0; i < 4; i++) {            // A: 128 rows
            const uint32_t so = so0 + (uint32_t)i * 32 * 128;
            cpa16(s + so, pA + (size_t)i * 32 * lda + k0);
        }
        #pragma unroll
        for (int i = 0; i < 4; i++) {            // B: 128 rows
            const uint32_t so = so0 + (uint32_t)i * 32 * 128;
            cpa16(s + 16384 + so, pB + (size_t)i * 32 * ldb + k0);
        }
        asm volatile("cp.async.commit_group;");
    };

    auto compute = [&](int st) {
        const uint32_t sa = sbase + (uint32_t)st * STAGE_B;
        const uint32_t sb = sa + 16384;
        #pragma unroll
        for (int ks = 0; ks < 4; ks++) {
            const uint32_t kb = ks * 32;
            uint32_t ah[2][4], bb[4][4];
            #pragma unroll
            for (int mt = 0; mt < 2; mt++) {
                const uint32_t o = aoffl + (uint32_t)(wm * 32 + mt * 16) * 128 + kb;
                ldmx4(ah[mt], sa + swz(o));
            }
            #pragma unroll
            for (int np = 0; np < 4; np++) {
                const uint32_t o = boffl + (uint32_t)(wn * 64 + np * 16) * 128 + kb;
                ldmx4(bb[np], sb + swz(o));
            }
            #pragma unroll
            for (int mt = 0; mt < 2; mt++)
                #pragma unroll
                for (int np = 0; np < 4; np++)
                    #pragma unroll
                    for (int h2 = 0; h2 < 2; h2++)
                        mma16816(acc[mt][np * 2 + h2], ah[mt],
                                 bb[np][h2 * 2], bb[np][h2 * 2 + 1]);
        }
    };

    // 3-stage pipeline; barrier precedes issue(c+2) so the stage being
    // overwritten ((c+2)%3 == (c-1)%3) is fully consumed by all warps.
    issue(0);
    if (nchunks > 1) issue(1);
    for (int c = 0; c < nchunks; c++) {
        if (c + 1 < nchunks) asm volatile("cp.async.wait_group 1;" ::: "memory");
        else                 asm volatile("cp.async.wait_group 0;" ::: "memory");
        __syncthreads();
        if (c + 2 < nchunks) issue(c + 2);
        compute(c - (c / 3) * 3);
    }

    // ---- epilogue ----
    const int r0l = lane >> 2, c0l = (lane & 3) * 2;
    #pragma unroll
    for (int mt = 0; mt < 2; mt++) {
        const int rowA = bm + wm * 32 + mt * 16 + r0l;
        #pragma unroll
        for (int nt = 0; nt < 8; nt++) {
            const int col = bn + wn * 64 + nt * 8 + c0l;
            #pragma unroll
            for (int hf = 0; hf < 2; hf++) {
                const int row = rowA + hf * 8;
                float v0 = acc[mt][nt][hf * 2 + 0];
                float v1 = acc[mt][nt][hf * 2 + 1];
                if (EPI == 0) {
                    const float2 bbv = *(const float2*)(bias + col);
                    v0 = tanhf(v0 + bbv.x); v1 = tanhf(v1 + bbv.y);
                    *(uint32_t*)(Ch + (size_t)row * N + col) =
                        pk2h(__float2half_rn(v0), __float2half_rn(v1));
                } else {
                    *(float2*)(Cp + (size_t)row * N + col) = make_float2(v0, v1);
                }
            }
        }
    }
}

// ---------------------------------------------------------------------------
// Weight transpose to fp16: W[K][N] -> T[N][K]
// ---------------------------------------------------------------------------
__global__ void k_tsplit(const float* __restrict__ W,
                         __half* __restrict__ T, int K, int N)
{
    __shared__ float t[32][33];
    const int n0 = blockIdx.x * 32, k0 = blockIdx.y * 32;
    for (int i = threadIdx.y; i < 32; i += 8)
        t[i][threadIdx.x] = W[(size_t)(k0 + i) * N + n0 + threadIdx.x];
    __syncthreads();
    for (int i = threadIdx.y; i < 32; i += 8) {
        float v = t[threadIdx.x][i];
        T[(size_t)(n0 + i) * K + k0 + threadIdx.x] = __float2half_rn(v);
    }
}

// ---------------------------------------------------------------------------
// Combine: dst = alpha*(p0+p1+bias) [+ addv], optional fp16 image of dst
// ---------------------------------------------------------------------------
__global__ void k_comb(float4* __restrict__ dst,
                       const float4* __restrict__ p0, const float4* __restrict__ p1,
                       const float4* __restrict__ bias4,
                       const float4* __restrict__ addv, float alpha,
                       uint2* __restrict__ oh)
{
    int i = blockIdx.x * 256 + threadIdx.x;
    float4 a = p0[i], b = p1[i], bb = bias4[i & 127];
    float4 v;
    v.x = alpha * (a.x + b.x + bb.x);
    v.y = alpha * (a.y + b.y + bb.y);
    v.z = alpha * (a.z + b.z + bb.z);
    v.w = alpha * (a.w + b.w + bb.w);
    if (addv) {
        float4 av = addv[i];
        v.x += av.x; v.y += av.y; v.z += av.z; v.w += av.w;
    }
    dst[i] = v;
    if (oh) oh[i] = pk4h(v);
}

// ---------------------------------------------------------------------------
// Elementwise kernels
// ---------------------------------------------------------------------------
__global__ void k_split(float4* __restrict__ o, uint2* __restrict__ oh,
                        const float4* __restrict__ src)
{
    int i = blockIdx.x * 256 + threadIdx.x;
    float4 v = src[i];
    o[i] = v;
    oh[i] = pk4h(v);
}

__global__ void k_axpy(float4* __restrict__ o, const float4* __restrict__ y,
                       const float4* __restrict__ k, float a)
{
    int i = blockIdx.x * 256 + threadIdx.x;
    float4 yv = y[i], kv = k[i];
    o[i] = make_float4(fmaf(a, kv.x, yv.x), fmaf(a, kv.y, yv.y),
                       fmaf(a, kv.z, yv.z), fmaf(a, kv.w, yv.w));
}

__global__ void k_axpy_sp(uint2* __restrict__ oh, const float4* __restrict__ y,
                          const float4* __restrict__ k, float a)
{
    int i = blockIdx.x * 256 + threadIdx.x;
    float4 yv = y[i], kv = k[i];
    float4 v = make_float4(fmaf(a, kv.x, yv.x), fmaf(a, kv.y, yv.y),
                           fmaf(a, kv.z, yv.z), fmaf(a, kv.w, yv.w));
    oh[i] = pk4h(v);
}

__global__ void k_acc(float4* __restrict__ o, const float4* __restrict__ p, float a)
{
    int i = blockIdx.x * 256 + threadIdx.x;
    float4 ov = o[i], pv = p[i];
    o[i] = make_float4(fmaf(a, pv.x, ov.x), fmaf(a, pv.y, ov.y),
                       fmaf(a, pv.z, ov.z), fmaf(a, pv.w, ov.w));
}

__global__ void k_acc_sp(float4* __restrict__ o, const float4* __restrict__ p,
                         float a, uint2* __restrict__ oh)
{
    int i = blockIdx.x * 256 + threadIdx.x;
    float4 ov = o[i], pv = p[i];
    float4 v = make_float4(fmaf(a, pv.x, ov.x), fmaf(a, pv.y, ov.y),
                           fmaf(a, pv.z, ov.z), fmaf(a, pv.w, ov.w));
    o[i] = v;
    oh[i] = pk4h(v);
}

__global__ void k_pred_sp(float4* __restrict__ o, const float4* __restrict__ y,
                          const float4* __restrict__ h0, const float4* __restrict__ h1,
                          const float4* __restrict__ h2, const float4* __restrict__ h3,
                          float c, uint2* __restrict__ oh)
{
    int i = blockIdx.x * 256 + threadIdx.x;
    float4 yv = y[i], a = h0[i], b = h1[i], d = h2[i], e = h3[i];
    float4 r;
    r.x = yv.x + c * (55.f * a.x - 59.f * b.x + 37.f * d.x - 9.f * e.x);
    r.y = yv.y + c * (55.f * a.y - 59.f * b.y + 37.f * d.y - 9.f * e.y);
    r.z = yv.z + c * (55.f * a.z - 59.f * b.z + 37.f * d.z - 9.f * e.z);
    r.w = yv.w + c * (55.f * a.w - 59.f * b.w + 37.f * d.w - 9.f * e.w);
    o[i] = r;
    oh[i] = pk4h(r);
}

__global__ void k_base(float4* __restrict__ o, const float4* __restrict__ y,
                       const float4* __restrict__ h0, const float4* __restrict__ h1,
                       const float4* __restrict__ h2, float c)
{
    int i = blockIdx.x * 256 + threadIdx.x;
    float4 yv = y[i], a = h0[i], b = h1[i], d = h2[i];
    float4 r;
    r.x = yv.x + c * (19.f * a.x - 5.f * b.x + d.x);
    r.y = yv.y + c * (19.f * a.y - 5.f * b.y + d.y);
    r.z = yv.z + c * (19.f * a.z - 5.f * b.z + d.z);
    r.w = yv.w + c * (19.f * a.w - 5.f * b.w + d.w);
    o[i] = r;
}

// ---------------------------------------------------------------------------
// Host orchestration
// ---------------------------------------------------------------------------
extern "C" void kernel_launch(void* const* d_in, const int* in_sizes, int n_in,
                              void* d_out, int out_size)
{
    const float* x  = (const float*)d_in[0];
    const float* W1 = (const float*)d_in[1];
    const float* b1 = (const float*)d_in[2];
    const float* W2 = (const float*)d_in[3];
    const float* b2 = (const float*)d_in[4];
    float* out = (float*)d_out;

    float *y, *acc, *kk, *pred, *base, *histbase, *part;
    __half *pin, *w1t, *w2t, *act;
    cudaGetSymbolAddress((void**)&y,        g_y);
    cudaGetSymbolAddress((void**)&acc,      g_acc);
    cudaGetSymbolAddress((void**)&kk,       g_kk);
    cudaGetSymbolAddress((void**)&pred,     g_pred);
    cudaGetSymbolAddress((void**)&base,     g_base);
    cudaGetSymbolAddress((void**)&histbase, g_hist);
    cudaGetSymbolAddress((void**)&part,     g_part);
    cudaGetSymbolAddress((void**)&pin,      g_pin);
    cudaGetSymbolAddress((void**)&w1t,      g_w1t);
    cudaGetSymbolAddress((void**)&w2t,      g_w2t);
    cudaGetSymbolAddress((void**)&act,      g_act);

    cudaFuncSetAttribute(gemm_cp<0>, cudaFuncAttributeMaxDynamicSharedMemorySize, GEMM_SMEM);
    cudaFuncSetAttribute(gemm_cp<1>, cudaFuncAttributeMaxDynamicSharedMemorySize, GEMM_SMEM);

    float* h[4];
    for (int i = 0; i < 4; i++) h[i] = histbase + (size_t)i * NSTATE;

    const float dt = 1.0f / (float)NSTEPS;
    const float c  = dt / 24.0f;

    const dim3 blk(256);
    const dim3 grid1(NH / 128, NB / 128);        // 16 x 32 = 512 CTAs
    const dim3 grid2(ND / 128, NB / 128, 2);     // 4 x 32 x 2 = 256 CTAs
    const int EG = NSTATE / 4 / 256;

    k_tsplit<<<dim3(NH / 32, ND / 32), dim3(32, 8)>>>(W1, w1t, ND, NH);
    k_tsplit<<<dim3(ND / 32, NH / 32), dim3(32, 8)>>>(W2, w2t, NH, ND);

    auto feval = [&](float* dstF, __half* dsth, float alpha, const float* addv) {
        gemm_cp<0><<<grid1, blk, GEMM_SMEM>>>(pin, ND, w1t, ND,
                                              ND / 64, 0, b1, act, nullptr, NH);
        gemm_cp<1><<<grid2, blk, GEMM_SMEM>>>(act, NH, w2t, NH,
                                              (NH / 2) / 64, NH / 2, nullptr,
                                              nullptr, part, ND);
        k_comb<<<EG, blk>>>((float4*)dstF, (const float4*)part,
                            (const float4*)(part + NSTATE), (const float4*)b2,
                            (const float4*)addv, alpha, (uint2*)dsth);
    };

    // y = x (fp32 + fp16 image)
    k_split<<<EG, blk>>>((float4*)y, (uint2*)pin, (const float4*)x);

    // ---- bootstrap: f(y0) -> h[3] ----
    feval(h[3], nullptr, 1.f, nullptr);

    // ---- 3 RK4 steps; k1 reused from most recent hist entry ----
    for (int s = 0; s < 3; s++) {
        float* k1 = h[3 - s];
        k_axpy   <<<EG, blk>>>((float4*)acc, (const float4*)y, (const float4*)k1, dt / 6.f);
        k_axpy_sp<<<EG, blk>>>((uint2*)pin,
                               (const float4*)y, (const float4*)k1, 0.5f * dt);
        feval(kk, nullptr, 1.f, nullptr);                                    // k2
        k_acc    <<<EG, blk>>>((float4*)acc, (const float4*)kk, dt / 3.f);
        k_axpy_sp<<<EG, blk>>>((uint2*)pin,
                               (const float4*)y, (const float4*)kk, 0.5f * dt);
        feval(kk, nullptr, 1.f, nullptr);                                    // k3
        k_acc    <<<EG, blk>>>((float4*)acc, (const float4*)kk, dt / 3.f);
        k_axpy_sp<<<EG, blk>>>((uint2*)pin,
                               (const float4*)y, (const float4*)kk, dt);
        feval(kk, nullptr, 1.f, nullptr);                                    // k4
        k_acc_sp <<<EG, blk>>>((float4*)acc, (const float4*)kk, dt / 6.f,
                               (uint2*)pin);
        { float* t = y; y = acc; acc = t; }
        feval(h[2 - s], nullptr, 1.f, nullptr);          // f(y_new) = next k1
    }

    // ---- 17 ABM4 predictor-corrector steps ----
    const int NABM = NSTEPS - 3;
    for (int i = 0; i < NABM; i++) {
        k_pred_sp<<<EG, blk>>>((float4*)pred, (const float4*)y,
                               (const float4*)h[0], (const float4*)h[1],
                               (const float4*)h[2], (const float4*)h[3], c,
                               (uint2*)pin);
        k_base<<<EG, blk>>>((float4*)base, (const float4*)y,
                            (const float4*)h[0], (const float4*)h[1],
                            (const float4*)h[2], c);
        for (int j = 0; j < NCORR; j++) {
            const bool last = (i == NABM - 1) && (j == NCORR - 1);
            if (last) feval(out,  nullptr,      9.f * c, base);
            else      feval(pred, (__half*)pin, 9.f * c, base);
        }
        if (i < NABM - 1) {
            feval(h[3], nullptr, 1.f, nullptr);          // f(pred)
            float* t = h[3]; h[3] = h[2]; h[2] = h[1]; h[1] = h[0]; h[0] = t;
            float* t2 = y; y = pred; pred = t2;
        }
    }
}

// round 17
// speedup vs baseline: 1.7320x; 1.0362x over previous
#include <cuda_runtime.h>
#include <cuda_fp16.h>
#include <cstdint>
#include <cstddef>

// ---------------------------------------------------------------------------
// Problem constants
// ---------------------------------------------------------------------------
constexpr int NB = 4096;
constexpr int ND = 512;
constexpr int NH = 2048;
constexpr int NSTATE = NB * ND;
constexpr int NSTEPS = 20;
constexpr int NCORR  = 3;

// ---------------------------------------------------------------------------
// Scratch (device globals)
// ---------------------------------------------------------------------------
__device__ float g_y[NSTATE];
__device__ float g_acc[NSTATE];
__device__ float g_kk[NSTATE];
__device__ float g_pred[NSTATE];
__device__ float g_base[NSTATE];
__device__ float g_hist[4 * NSTATE];

__device__ __half g_part[2 * NSTATE];           // split-K partials (fp16)
__device__ __half g_pin[NSTATE];                // feval input (fp16)
__device__ __half g_w1t[(size_t)NH * ND];       // W1^T fp16
__device__ __half g_w2t[(size_t)ND * NH];       // W2^T fp16
__device__ __half g_act[(size_t)NB * NH];       // tanh activations fp16

// ---------------------------------------------------------------------------
// Helpers
// ---------------------------------------------------------------------------
__device__ __forceinline__ uint32_t smem_u32(const void* p) {
    uint32_t a;
    asm("{ .reg .u64 t; cvta.to.shared.u64 t, %1; cvt.u32.u64 %0, t; }"
        : "=r"(a) : "l"(p));
    return a;
}

__device__ __forceinline__ uint32_t swz(uint32_t o) {
    return o ^ ((o >> 3) & 0x70);
}

__device__ __forceinline__ void cpa16(uint32_t s, const void* g) {
    asm volatile("cp.async.cg.shared.global [%0], [%1], 16;" :: "r"(s), "l"(g));
}

__device__ __forceinline__ void ldmx4(uint32_t r[4], uint32_t addr) {
    asm volatile("ldmatrix.sync.aligned.m8n8.x4.shared.b16 {%0,%1,%2,%3}, [%4];"
                 : "=r"(r[0]), "=r"(r[1]), "=r"(r[2]), "=r"(r[3]) : "r"(addr));
}

__device__ __forceinline__ void mma16816(float d[4], const uint32_t a[4],
                                         uint32_t b0, uint32_t b1) {
    asm volatile(
        "mma.sync.aligned.m16n8k16.row.col.f32.f16.f16.f32 "
        "{%0,%1,%2,%3}, {%4,%5,%6,%7}, {%8,%9}, {%0,%1,%2,%3};"
        : "+f"(d[0]), "+f"(d[1]), "+f"(d[2]), "+f"(d[3])
        : "r"(a[0]), "r"(a[1]), "r"(a[2]), "r"(a[3]), "r"(b0), "r"(b1));
}

__device__ __forceinline__ uint32_t pk2h(__half a, __half b) {
    __half2 t = __halves2half2(a, b);
    return *reinterpret_cast<uint32_t*>(&t);
}
__device__ __forceinline__ uint2 pk4h(float4 v) {
    uint2 r;
    r.x = pk2h(__float2half_rn(v.x), __float2half_rn(v.y));
    r.y = pk2h(__float2half_rn(v.z), __float2half_rn(v.w));
    return r;
}
__device__ __forceinline__ float4 ld4h(const uint2* p, int i) {
    uint2 u = p[i];
    __half2 a = *reinterpret_cast<__half2*>(&u.x);
    __half2 b = *reinterpret_cast<__half2*>(&u.y);
    float2 fa = __half22float2(a), fb = __half22float2(b);
    return make_float4(fa.x, fa.y, fb.x, fb.y);
}

// ---------------------------------------------------------------------------
// Single-product fp16 HMMA GEMM (A fp16, B fp16, fp32 accum).
// CTA tile 128x128, 8 warps of 32x64, 2 CTAs/SM. 3-stage cp.async ring.
//   EPI 0: C = tanh(acc + bias) -> fp16
//   EPI 1: fp16 partial store (split-K slice via blockIdx.z)
// ---------------------------------------------------------------------------
constexpr int STAGE_B = 32768;
constexpr int GEMM_SMEM = 3 * STAGE_B;   // 98304

template <int EPI>
__global__ __launch_bounds__(256, 2)
void gemm_cp(const __half* __restrict__ Ap, int lda,
             const __half* __restrict__ Bp, int ldb,
             int nchunks, int kslice,
             const float* __restrict__ bias,
             __half* __restrict__ Ch,
             __half* __restrict__ Cph,
             int N)
{
    extern __shared__ char smem[];
    const uint32_t sbase = smem_u32(smem);
    const int tid = threadIdx.x;
    const int wid = tid >> 5, lane = tid & 31;
    const int wm = wid & 3;            // 4 row-blocks of 32
    const int wn = wid >> 2;           // 2 col-blocks of 64
    const int bm = blockIdx.y * 128, bn = blockIdx.x * 128;
    const int koff = blockIdx.z * kslice;
    if (EPI == 1) Cph += (size_t)blockIdx.z * NSTATE;

    const int cr = tid >> 3;
    const int cq = tid & 7;
    const uint32_t so0 = swz((uint32_t)cr * 128 + cq * 16);

    const __half* pA = Ap + (size_t)(bm + cr) * lda + koff + cq * 8;
    const __half* pB = Bp + (size_t)(bn + cr) * ldb + koff + cq * 8;

    const int bg = lane >> 3;
    const uint32_t boffl = (uint32_t)((lane & 7) + ((bg & 2) ? 8 : 0)) * 128
                         + (bg & 1) * 16;
    const uint32_t aoffl = (uint32_t)(lane & 15) * 128 + (lane >> 4) * 16;

    float acc[2][8][4];
    #pragma unroll
    for (int mt = 0; mt < 2; mt++)
        #pragma unroll
        for (int nt = 0; nt < 8; nt++)
            #pragma unroll
            for (int q = 0; q < 4; q++) acc[mt][nt][q] = 0.f;

    auto issue = [&](int c) {
        const int st = c - (c / 3) * 3;
        const uint32_t s = sbase + (uint32_t)st * STAGE_B;
        const int k0 = c << 6;
        #pragma unroll
        for (int i = 0; i < 4; i++) {
            const uint32_t so = so0 + (uint32_t)i * 32 * 128;
            cpa16(s + so, pA + (size_t)i * 32 * lda + k0);
        }
        #pragma unroll
        for (int i = 0; i < 4; i++) {
            const uint32_t so = so0 + (uint32_t)i * 32 * 128;
            cpa16(s + 16384 + so, pB + (size_t)i * 32 * ldb + k0);
        }
        asm volatile("cp.async.commit_group;");
    };

    auto compute = [&](int st) {
        const uint32_t sa = sbase + (uint32_t)st * STAGE_B;
        const uint32_t sb = sa + 16384;
        #pragma unroll
        for (int ks = 0; ks < 4; ks++) {
            const uint32_t kb = ks * 32;
            uint32_t ah[2][4], bb[4][4];
            #pragma unroll
            for (int mt = 0; mt < 2; mt++) {
                const uint32_t o = aoffl + (uint32_t)(wm * 32 + mt * 16) * 128 + kb;
                ldmx4(ah[mt], sa + swz(o));
            }
            #pragma unroll
            for (int np = 0; np < 4; np++) {
                const uint32_t o = boffl + (uint32_t)(wn * 64 + np * 16) * 128 + kb;
                ldmx4(bb[np], sb + swz(o));
            }
            #pragma unroll
            for (int mt = 0; mt < 2; mt++)
                #pragma unroll
                for (int np = 0; np < 4; np++)
                    #pragma unroll
                    for (int h2 = 0; h2 < 2; h2++)
                        mma16816(acc[mt][np * 2 + h2], ah[mt],
                                 bb[np][h2 * 2], bb[np][h2 * 2 + 1]);
        }
    };

    issue(0);
    if (nchunks > 1) issue(1);
    for (int c = 0; c < nchunks; c++) {
        if (c + 1 < nchunks) asm volatile("cp.async.wait_group 1;" ::: "memory");
        else                 asm volatile("cp.async.wait_group 0;" ::: "memory");
        __syncthreads();
        if (c + 2 < nchunks) issue(c + 2);
        compute(c - (c / 3) * 3);
    }

    // ---- epilogue ----
    const int r0l = lane >> 2, c0l = (lane & 3) * 2;
    #pragma unroll
    for (int mt = 0; mt < 2; mt++) {
        const int rowA = bm + wm * 32 + mt * 16 + r0l;
        #pragma unroll
        for (int nt = 0; nt < 8; nt++) {
            const int col = bn + wn * 64 + nt * 8 + c0l;
            #pragma unroll
            for (int hf = 0; hf < 2; hf++) {
                const int row = rowA + hf * 8;
                float v0 = acc[mt][nt][hf * 2 + 0];
                float v1 = acc[mt][nt][hf * 2 + 1];
                if (EPI == 0) {
                    const float2 bbv = *(const float2*)(bias + col);
                    v0 = tanhf(v0 + bbv.x); v1 = tanhf(v1 + bbv.y);
                    *(uint32_t*)(Ch + (size_t)row * N + col) =
                        pk2h(__float2half_rn(v0), __float2half_rn(v1));
                } else {
                    *(uint32_t*)(Cph + (size_t)row * N + col) =
                        pk2h(__float2half_rn(v0), __float2half_rn(v1));
                }
            }
        }
    }
}

// ---------------------------------------------------------------------------
// Weight transpose to fp16: W[K][N] -> T[N][K]
// ---------------------------------------------------------------------------
__global__ void k_tsplit(const float* __restrict__ W,
                         __half* __restrict__ T, int K, int N)
{
    __shared__ float t[32][33];
    const int n0 = blockIdx.x * 32, k0 = blockIdx.y * 32;
    for (int i = threadIdx.y; i < 32; i += 8)
        t[i][threadIdx.x] = W[(size_t)(k0 + i) * N + n0 + threadIdx.x];
    __syncthreads();
    for (int i = threadIdx.y; i < 32; i += 8) {
        float v = t[threadIdx.x][i];
        T[(size_t)(n0 + i) * K + k0 + threadIdx.x] = __float2half_rn(v);
    }
}

// ---------------------------------------------------------------------------
// Combine: dst = alpha*(p0+p1+bias) [+ addv], optional fp16 image of dst
// (p0/p1 are fp16 partials)
// ---------------------------------------------------------------------------
__global__ void k_comb(float4* __restrict__ dst,
                       const uint2* __restrict__ p0, const uint2* __restrict__ p1,
                       const float4* __restrict__ bias4,
                       const float4* __restrict__ addv, float alpha,
                       uint2* __restrict__ oh)
{
    int i = blockIdx.x * 256 + threadIdx.x;
    float4 a = ld4h(p0, i), b = ld4h(p1, i), bb = bias4[i & 127];
    float4 v;
    v.x = alpha * (a.x + b.x + bb.x);
    v.y = alpha * (a.y + b.y + bb.y);
    v.z = alpha * (a.z + b.z + bb.z);
    v.w = alpha * (a.w + b.w + bb.w);
    if (addv) {
        float4 av = addv[i];
        v.x += av.x; v.y += av.y; v.z += av.z; v.w += av.w;
    }
    dst[i] = v;
    if (oh) oh[i] = pk4h(v);
}

// ---------------------------------------------------------------------------
// Fused: f_new = p0+p1+b2 -> h3w;  pred_next = y + c(55f -59h0 +37h1 -9h2);
// base_next = y + c(19f -5h0 +h1);  pin = fp16(pred_next)
// ---------------------------------------------------------------------------
__global__ void k_comb_pb(float4* __restrict__ h3w, float4* __restrict__ predw,
                          uint2* __restrict__ pin, float4* __restrict__ basew,
                          const uint2* __restrict__ p0, const uint2* __restrict__ p1,
                          const float4* __restrict__ bias4,
                          const float4* __restrict__ ycur,
                          const float4* __restrict__ h0,
                          const float4* __restrict__ h1,
                          const float4* __restrict__ h2, float c)
{
    int i = blockIdx.x * 256 + threadIdx.x;
    float4 a = ld4h(p0, i), b = ld4h(p1, i), bb = bias4[i & 127];
    float4 f;
    f.x = a.x + b.x + bb.x;  f.y = a.y + b.y + bb.y;
    f.z = a.z + b.z + bb.z;  f.w = a.w + b.w + bb.w;
    h3w[i] = f;
    float4 yv = ycur[i], v0 = h0[i], v1 = h1[i], v2 = h2[i];
    float4 pr, bs;
    pr.x = yv.x + c * (55.f * f.x - 59.f * v0.x + 37.f * v1.x - 9.f * v2.x);
    pr.y = yv.y + c * (55.f * f.y - 59.f * v0.y + 37.f * v1.y - 9.f * v2.y);
    pr.z = yv.z + c * (55.f * f.z - 59.f * v0.z + 37.f * v1.z - 9.f * v2.z);
    pr.w = yv.w + c * (55.f * f.w - 59.f * v0.w + 37.f * v1.w - 9.f * v2.w);
    bs.x = yv.x + c * (19.f * f.x - 5.f * v0.x + v1.x);
    bs.y = yv.y + c * (19.f * f.y - 5.f * v0.y + v1.y);
    bs.z = yv.z + c * (19.f * f.z - 5.f * v0.z + v1.z);
    bs.w = yv.w + c * (19.f * f.w - 5.f * v0.w + v1.w);
    predw[i] = pr;
    basew[i] = bs;
    pin[i] = pk4h(pr);
}

// ---------------------------------------------------------------------------
// Initial pred/base from full history: pred = y + c(55h0-59h1+37h2-9h3);
// base = y + c(19h0-5h1+h2); pin = fp16(pred)
// ---------------------------------------------------------------------------
__global__ void k_predbase(float4* __restrict__ predw, uint2* __restrict__ pin,
                           float4* __restrict__ basew,
                           const float4* __restrict__ y,
                           const float4* __restrict__ h0,
                           const float4* __restrict__ h1,
                           const float4* __restrict__ h2,
                           const float4* __restrict__ h3, float c)
{
    int i = blockIdx.x * 256 + threadIdx.x;
    float4 yv = y[i], a = h0[i], b = h1[i], d = h2[i], e = h3[i];
    float4 pr, bs;
    pr.x = yv.x + c * (55.f * a.x - 59.f * b.x + 37.f * d.x - 9.f * e.x);
    pr.y = yv.y + c * (55.f * a.y - 59.f * b.y + 37.f * d.y - 9.f * e.y);
    pr.z = yv.z + c * (55.f * a.z - 59.f * b.z + 37.f * d.z - 9.f * e.z);
    pr.w = yv.w + c * (55.f * a.w - 59.f * b.w + 37.f * d.w - 9.f * e.w);
    bs.x = yv.x + c * (19.f * a.x - 5.f * b.x + d.x);
    bs.y = yv.y + c * (19.f * a.y - 5.f * b.y + d.y);
    bs.z = yv.z + c * (19.f * a.z - 5.f * b.z + d.z);
    bs.w = yv.w + c * (19.f * a.w - 5.f * b.w + d.w);
    predw[i] = pr;
    basew[i] = bs;
    pin[i] = pk4h(pr);
}

// ---------------------------------------------------------------------------
// RK4 fused elementwise
// ---------------------------------------------------------------------------
__global__ void k_split(float4* __restrict__ o, uint2* __restrict__ oh,
                        const float4* __restrict__ src)
{
    int i = blockIdx.x * 256 + threadIdx.x;
    float4 v = src[i];
    o[i] = v;
    oh[i] = pk4h(v);
}

// acc = y + aa*k; pin = fp16(y + ap*k)
__global__ void k_axpy2(float4* __restrict__ accw, uint2* __restrict__ pin,
                        const float4* __restrict__ y, const float4* __restrict__ k,
                        float aa, float ap)
{
    int i = blockIdx.x * 256 + threadIdx.x;
    float4 yv = y[i], kv = k[i];
    accw[i] = make_float4(fmaf(aa, kv.x, yv.x), fmaf(aa, kv.y, yv.y),
                          fmaf(aa, kv.z, yv.z), fmaf(aa, kv.w, yv.w));
    float4 v = make_float4(fmaf(ap, kv.x, yv.x), fmaf(ap, kv.y, yv.y),
                           fmaf(ap, kv.z, yv.z), fmaf(ap, kv.w, yv.w));
    pin[i] = pk4h(v);
}

// acc += aa*k; pin = fp16(y + ap*k)
__global__ void k_acc2(float4* __restrict__ accio, uint2* __restrict__ pin,
                       const float4* __restrict__ y, const float4* __restrict__ k,
                       float aa, float ap)
{
    int i = blockIdx.x * 256 + threadIdx.x;
    float4 av = accio[i], yv = y[i], kv = k[i];
    accio[i] = make_float4(fmaf(aa, kv.x, av.x), fmaf(aa, kv.y, av.y),
                           fmaf(aa, kv.z, av.z), fmaf(aa, kv.w, av.w));
    float4 v = make_float4(fmaf(ap, kv.x, yv.x), fmaf(ap, kv.y, yv.y),
                           fmaf(ap, kv.z, yv.z), fmaf(ap, kv.w, yv.w));
    pin[i] = pk4h(v);
}

// acc += a*k; pin = fp16(acc_new)
__global__ void k_acc_sp(float4* __restrict__ accio, const float4* __restrict__ k,
                         float a, uint2* __restrict__ pin)
{
    int i = blockIdx.x * 256 + threadIdx.x;
    float4 av = accio[i], kv = k[i];
    float4 v = make_float4(fmaf(a, kv.x, av.x), fmaf(a, kv.y, av.y),
                           fmaf(a, kv.z, av.z), fmaf(a, kv.w, av.w));
    accio[i] = v;
    pin[i] = pk4h(v);
}

// ---------------------------------------------------------------------------
// Host orchestration
// ---------------------------------------------------------------------------
extern "C" void kernel_launch(void* const* d_in, const int* in_sizes, int n_in,
                              void* d_out, int out_size)
{
    const float* x  = (const float*)d_in[0];
    const float* W1 = (const float*)d_in[1];
    const float* b1 = (const float*)d_in[2];
    const float* W2 = (const float*)d_in[3];
    const float* b2 = (const float*)d_in[4];
    float* out = (float*)d_out;

    float *y, *acc, *kk, *pred, *base, *histbase;
    __half *part, *pin, *w1t, *w2t, *act;
    cudaGetSymbolAddress((void**)&y,        g_y);
    cudaGetSymbolAddress((void**)&acc,      g_acc);
    cudaGetSymbolAddress((void**)&kk,       g_kk);
    cudaGetSymbolAddress((void**)&pred,     g_pred);
    cudaGetSymbolAddress((void**)&base,     g_base);
    cudaGetSymbolAddress((void**)&histbase, g_hist);
    cudaGetSymbolAddress((void**)&part,     g_part);
    cudaGetSymbolAddress((void**)&pin,      g_pin);
    cudaGetSymbolAddress((void**)&w1t,      g_w1t);
    cudaGetSymbolAddress((void**)&w2t,      g_w2t);
    cudaGetSymbolAddress((void**)&act,      g_act);

    cudaFuncSetAttribute(gemm_cp<0>, cudaFuncAttributeMaxDynamicSharedMemorySize, GEMM_SMEM);
    cudaFuncSetAttribute(gemm_cp<1>, cudaFuncAttributeMaxDynamicSharedMemorySize, GEMM_SMEM);

    float* h[4];
    for (int i = 0; i < 4; i++) h[i] = histbase + (size_t)i * NSTATE;

    const float dt = 1.0f / (float)NSTEPS;
    const float c  = dt / 24.0f;

    const dim3 blk(256);
    const dim3 grid1(NH / 128, NB / 128);        // 512 CTAs
    const dim3 grid2(ND / 128, NB / 128, 2);     // 256 CTAs, split-K
    const int EG = NSTATE / 4 / 256;

    const uint2* p0 = (const uint2*)part;
    const uint2* p1 = (const uint2*)(part + NSTATE);

    k_tsplit<<<dim3(NH / 32, ND / 32), dim3(32, 8)>>>(W1, w1t, ND, NH);
    k_tsplit<<<dim3(ND / 32, NH / 32), dim3(32, 8)>>>(W2, w2t, NH, ND);

    auto run_gemms = [&]() {
        gemm_cp<0><<<grid1, blk, GEMM_SMEM>>>(pin, ND, w1t, ND,
                                              ND / 64, 0, b1, act, nullptr, NH);
        gemm_cp<1><<<grid2, blk, GEMM_SMEM>>>(act, NH, w2t, NH,
                                              (NH / 2) / 64, NH / 2, nullptr,
                                              nullptr, part, ND);
    };

    // y = x (fp32 + fp16 image)
    k_split<<<EG, blk>>>((float4*)y, (uint2*)pin, (const float4*)x);

    // ---- bootstrap: f(y0) -> h[3] ----
    run_gemms();
    k_comb<<<EG, blk>>>((float4*)h[3], p0, p1, (const float4*)b2,
                        nullptr, 1.f, nullptr);

    // ---- 3 RK4 steps; k1 reused from most recent hist entry ----
    for (int s = 0; s < 3; s++) {
        float* k1 = h[3 - s];
        k_axpy2<<<EG, blk>>>((float4*)acc, (uint2*)pin,
                             (const float4*)y, (const float4*)k1, dt / 6.f, 0.5f * dt);
        run_gemms();                                                         // k2
        k_comb<<<EG, blk>>>((float4*)kk, p0, p1, (const float4*)b2, nullptr, 1.f, nullptr);
        k_acc2<<<EG, blk>>>((float4*)acc, (uint2*)pin,
                            (const float4*)y, (const float4*)kk, dt / 3.f, 0.5f * dt);
        run_gemms();                                                         // k3
        k_comb<<<EG, blk>>>((float4*)kk, p0, p1, (const float4*)b2, nullptr, 1.f, nullptr);
        k_acc2<<<EG, blk>>>((float4*)acc, (uint2*)pin,
                            (const float4*)y, (const float4*)kk, dt / 3.f, dt);
        run_gemms();                                                         // k4
        k_comb<<<EG, blk>>>((float4*)kk, p0, p1, (const float4*)b2, nullptr, 1.f, nullptr);
        k_acc_sp<<<EG, blk>>>((float4*)acc, (const float4*)kk, dt / 6.f, (uint2*)pin);
        { float* t = y; y = acc; acc = t; }
        run_gemms();                                  // f(y_new) = next k1
        k_comb<<<EG, blk>>>((float4*)h[2 - s], p0, p1, (const float4*)b2,
                            nullptr, 1.f, nullptr);
    }

    // ---- 17 ABM4 predictor-corrector steps ----
    const int NABM = NSTEPS - 3;
    k_predbase<<<EG, blk>>>((float4*)pred, (uint2*)pin, (float4*)base,
                            (const float4*)y, (const float4*)h[0], (const float4*)h[1],
                            (const float4*)h[2], (const float4*)h[3], c);
    for (int i = 0; i < NABM; i++) {
        for (int j = 0; j < NCORR; j++) {
            run_gemms();
            const bool last = (i == NABM - 1) && (j == NCORR - 1);
            if (last)
                k_comb<<<EG, blk>>>((float4*)out, p0, p1, (const float4*)b2,
                                    (const float4*)base, 9.f * c, nullptr);
            else
                k_comb<<<EG, blk>>>((float4*)pred, p0, p1, (const float4*)b2,
                                    (const float4*)base, 9.f * c, (uint2*)pin);
        }
        if (i < NABM - 1) {
            run_gemms();                              // f(pred) via pin
            // f_new -> h[3]; pred_next -> old y buffer; base/pin updated
            k_comb_pb<<<EG, blk>>>((float4*)h[3], (float4*)y, (uint2*)pin,
                                   (float4*)base, p0, p1, (const float4*)b2,
                                   (const float4*)pred, (const float4*)h[0],
                                   (const float4*)h[1], (const float4*)h[2], c);
            float* t = h[3]; h[3] = h[2]; h[2] = h[1]; h[1] = h[0]; h[0] = t;
            float* t2 = y; y = pred; pred = t2;       // y <- state, pred <- pred_next
        }
    }
}